// round 13
// baseline (speedup 1.0000x reference)
#include <cuda_runtime.h>
#include <cuda_bf16.h>
#include <math.h>
#include <stdint.h>

// Problem constants
#define Hd 1024
#define Ld 4
#define DI 2048
#define Nst 16
#define Kc 4
#define BATCH 2
#define SEQ 1024
#define TOK (BATCH*SEQ)          // 2048 tokens

// ---------------- scratch buffers (device globals; no allocation) -------------
__device__ float g_x  [TOK*Hd];
__device__ float g_xr [TOK*2*DI];
__device__ float g_c1 [TOK*DI];
__device__ float g_xi [TOK*DI];
__device__ float g_proj[TOK*33];
__device__ float g_y  [TOK*DI];
__device__ float g_t1 [TOK*Hd];   // unused fp32 (kept for EPI signatures)

// bf16 hi/lo operand buffers
// weights packed: [in_proj L*2DI*Hd][out_proj L*Hd*DI][op1 Hd*Hd][op2 Hd*Hd]
#define WOFF_IP 0
#define WOFF_OP (Ld*2*DI*Hd)                    // 16777216
#define WOFF_M1 (WOFF_OP + Ld*Hd*DI)            // 25165824
#define WOFF_M2 (WOFF_M1 + Hd*Hd)               // 26214400
#define WTOT    (WOFF_M2 + Hd*Hd)               // 27262976
__device__ __nv_bfloat16 g_wh[WTOT];
__device__ __nv_bfloat16 g_wl[WTOT];
__device__ __nv_bfloat16 g_ah[TOK*DI];
__device__ __nv_bfloat16 g_al[TOK*DI];
__device__ __nv_bfloat16 g_bh[TOK*Hd];
__device__ __nv_bfloat16 g_bl[TOK*Hd];

// ---------------- helpers ----------------------------------------------------
__device__ __forceinline__ float sigmoidf_(float x){ return 1.f/(1.f+__expf(-x)); }
__device__ __forceinline__ float siluf_(float x){ return x * (1.f/(1.f+__expf(-x))); }
__device__ __forceinline__ float geluf_(float x){ return 0.5f*x*(1.f+erff(x*0.70710678118654752f)); }

__device__ __forceinline__ uint32_t smem_u32(const void* p){
    uint32_t a;
    asm("{ .reg .u64 t; cvta.to.shared.u64 t, %1; cvt.u32.u64 %0, t; }" : "=r"(a) : "l"(p));
    return a;
}
__device__ __forceinline__ void ldsm_x4(uint32_t* r, uint32_t addr){
    asm volatile("ldmatrix.sync.aligned.m8n8.x4.shared.b16 {%0,%1,%2,%3}, [%4];"
        : "=r"(r[0]), "=r"(r[1]), "=r"(r[2]), "=r"(r[3]) : "r"(addr));
}
__device__ __forceinline__ void ldsm_x2(uint32_t* r, uint32_t addr){
    asm volatile("ldmatrix.sync.aligned.m8n8.x2.shared.b16 {%0,%1}, [%2];"
        : "=r"(r[0]), "=r"(r[1]) : "r"(addr));
}
__device__ __forceinline__ void mma_bf16(float* c, const uint32_t* a, const uint32_t* b){
    asm volatile(
        "mma.sync.aligned.m16n8k16.row.col.f32.bf16.bf16.f32 "
        "{%0,%1,%2,%3}, {%4,%5,%6,%7}, {%8,%9}, {%0,%1,%2,%3};"
        : "+f"(c[0]), "+f"(c[1]), "+f"(c[2]), "+f"(c[3])
        : "r"(a[0]), "r"(a[1]), "r"(a[2]), "r"(a[3]), "r"(b[0]), "r"(b[1]));
}
__device__ __forceinline__ void cp16(uint32_t s, const void* g){
    asm volatile("cp.async.cg.shared.global [%0], [%1], 16;" :: "r"(s), "l"(g));
}
__device__ __forceinline__ void cp_commit(){
    asm volatile("cp.async.commit_group;" ::: "memory");
}
template<int N> __device__ __forceinline__ void cp_wait(){
    asm volatile("cp.async.wait_group %0;" :: "n"(N) : "memory");
}
__device__ __forceinline__ void split_hl(float v, __nv_bfloat16& h, __nv_bfloat16& l){
    h = __float2bfloat16(v);
    l = __float2bfloat16(v - __bfloat162float(h));
}

// ---------------- weight/activation fp32 -> bf16 hi/lo conversion ------------
__global__ void __launch_bounds__(256) cvt_hilo_k(
    const float* __restrict__ src, __nv_bfloat16* __restrict__ hi,
    __nv_bfloat16* __restrict__ lo, int n)
{
    int i = (blockIdx.x*256 + threadIdx.x)*4;
    if (i >= n) return;
    float4 v = *(const float4*)(src + i);
    __nv_bfloat16 h0,h1,h2,h3,l0,l1,l2,l3;
    split_hl(v.x,h0,l0); split_hl(v.y,h1,l1);
    split_hl(v.z,h2,l2); split_hl(v.w,h3,l3);
    __nv_bfloat162 hh0; hh0.x=h0; hh0.y=h1;
    __nv_bfloat162 hh1; hh1.x=h2; hh1.y=h3;
    __nv_bfloat162 ll0; ll0.x=l0; ll0.y=l1;
    __nv_bfloat162 ll1; ll1.x=l2; ll1.y=l3;
    *(uint2*)(hi+i) = make_uint2(*(uint32_t*)&hh0, *(uint32_t*)&hh1);
    *(uint2*)(lo+i) = make_uint2(*(uint32_t*)&ll0, *(uint32_t*)&ll1);
}

// ---------------- tensor-core GEMM NT, bf16 hi/lo operands --------------------
// C[m,n] = sum_k A[m,k]*B[n,k]; operands pre-split hi/lo bf16, K-major rows.
#define BM 128
#define BN 128
#define GBK 32                 // bf16 K elems per chunk
#define GP 80                  // byte pitch per smem row (40 bf16)
#define GTILE (128*GP)         // 10240 B
#define ST_AHI 0
#define ST_ALO (1*GTILE)
#define ST_BHI (2*GTILE)
#define ST_BLO (3*GTILE)
#define GSTG (4*GTILE)         // 40960 B per stage
#define GSM  (3*GSTG)          // 122880 B

// EPI: 0 none(fp32 C) | 1 gelu(acc+bias)->hi/lo | 2 acc+R1 (fp32) | 3 acc+bias+R1 (fp32)
template<int EPI>
__global__ void __launch_bounds__(256, 1) mma_gemm_nt(
    const __nv_bfloat16* __restrict__ Ahi, const __nv_bfloat16* __restrict__ Alo,
    const __nv_bfloat16* __restrict__ Bhi, const __nv_bfloat16* __restrict__ Blo,
    float* __restrict__ C, int M, int N, int K,
    const float* __restrict__ bias, const float* __restrict__ R1,
    __nv_bfloat16* __restrict__ Oh, __nv_bfloat16* __restrict__ Ol)
{
    extern __shared__ char smem[];
    const uint32_t smb = smem_u32(smem);
    const int tid  = threadIdx.x;
    const int wid  = tid >> 5;
    const int lane = tid & 31;
    const int bm = blockIdx.y * BM;
    const int bn = blockIdx.x * BN;
    const int warp_m = (wid >> 2) * 64;
    const int warp_n = (wid & 3) * 32;

    // cp.async mapping: row = tid/2, half = tid&1 (32B each)
    const int grow = tid >> 1;
    const int ghalf = tid & 1;
    const uint32_t soff = (uint32_t)grow*GP + (uint32_t)ghalf*32;
    const size_t aBase = (size_t)(bm + grow)*K + ghalf*16;
    const size_t bBase = (size_t)(bn + grow)*K + ghalf*16;

    // ldmatrix lane offsets (byte, within a tile) — verified mapping from R11
    const int a_r  = ((lane >> 3) & 1)*8 + (lane & 7);
    const int a_k8 = (lane >> 4) * 8;
    const uint32_t a_lane_off = (uint32_t)(warp_m + a_r)*GP + (uint32_t)a_k8*2;
    const int l16  = lane & 15;
    const uint32_t b_lane_off = (uint32_t)(warp_n + (l16 & 7))*GP + (uint32_t)(l16 >> 3)*16;

    float acc[4][4][4];
    #pragma unroll
    for (int i=0;i<4;i++)
        #pragma unroll
        for (int j=0;j<4;j++)
            #pragma unroll
            for (int q=0;q<4;q++) acc[i][j][q]=0.f;

    const int NK = K / GBK;

    auto load_stage = [&](int s, int kc){
        uint32_t base = smb + s*GSTG;
        size_t ka = aBase + (size_t)kc*GBK;
        size_t kb = bBase + (size_t)kc*GBK;
        cp16(base+ST_AHI+soff,    Ahi+ka);  cp16(base+ST_AHI+soff+16, Ahi+ka+8);
        cp16(base+ST_ALO+soff,    Alo+ka);  cp16(base+ST_ALO+soff+16, Alo+ka+8);
        cp16(base+ST_BHI+soff,    Bhi+kb);  cp16(base+ST_BHI+soff+16, Bhi+kb+8);
        cp16(base+ST_BLO+soff,    Blo+kb);  cp16(base+ST_BLO+soff+16, Blo+kb+8);
        cp_commit();
    };
    auto compute_stage = [&](int s){
        uint32_t base = smb + s*GSTG;
        #pragma unroll
        for (int kk=0; kk<GBK; kk+=16){
            uint32_t ahi[4][4], alo[4][4], bhi[4][2], blo[4][2];
            #pragma unroll
            for (int tm=0; tm<4; tm++){
                uint32_t o = base + a_lane_off + (uint32_t)tm*16*GP + (uint32_t)kk*2;
                ldsm_x4(ahi[tm], o + ST_AHI);
                ldsm_x4(alo[tm], o + ST_ALO);
            }
            #pragma unroll
            for (int tn=0; tn<4; tn++){
                uint32_t o = base + b_lane_off + (uint32_t)tn*8*GP + (uint32_t)kk*2;
                ldsm_x2(bhi[tn], o + ST_BHI);
                ldsm_x2(blo[tn], o + ST_BLO);
            }
            #pragma unroll
            for (int tm=0; tm<4; tm++)
                #pragma unroll
                for (int tn=0; tn<4; tn++){
                    mma_bf16(acc[tm][tn], ahi[tm], bhi[tn]);
                    mma_bf16(acc[tm][tn], ahi[tm], blo[tn]);
                    mma_bf16(acc[tm][tn], alo[tm], bhi[tn]);
                }
        }
    };

    // prologue: 2 stages in flight
    load_stage(0, 0);
    load_stage(1, 1);

    for (int kc=0; kc<NK; kc++){
        if (kc == NK-1) cp_wait<0>(); else cp_wait<1>();
        __syncthreads();
        if (kc+2 < NK) load_stage((kc+2)%3, kc+2);
        compute_stage(kc%3);
        __syncthreads();
    }

    // epilogue
    const int er = lane >> 2;
    const int ec = (lane & 3) * 2;
    #pragma unroll
    for (int tm=0; tm<4; tm++){
        #pragma unroll
        for (int tn=0; tn<4; tn++){
            int m0 = bm + warp_m + tm*16 + er;
            int n0 = bn + warp_n + tn*8 + ec;
            float* cr = acc[tm][tn];
            #pragma unroll
            for (int h=0; h<2; h++){
                int m = m0 + h*8;
                size_t idx = (size_t)m*N + n0;
                float v0 = cr[h*2+0], v1 = cr[h*2+1];
                if (EPI==1){
                    v0 = geluf_(v0 + bias[n0]); v1 = geluf_(v1 + bias[n0+1]);
                    __nv_bfloat16 h0,h1,l0,l1;
                    split_hl(v0,h0,l0); split_hl(v1,h1,l1);
                    __nv_bfloat162 hh; hh.x=h0; hh.y=h1;
                    __nv_bfloat162 ll; ll.x=l0; ll.y=l1;
                    *(uint32_t*)&Oh[idx] = *(uint32_t*)&hh;
                    *(uint32_t*)&Ol[idx] = *(uint32_t*)&ll;
                } else {
                    if (EPI==2){ v0 += R1[idx]; v1 += R1[idx+1]; }
                    else if (EPI==3){ v0 += bias[n0] + R1[idx]; v1 += bias[n0+1] + R1[idx+1]; }
                    float2 o; o.x=v0; o.y=v1;
                    *(float2*)&C[idx] = o;
                }
            }
        }
    }
}

// ---------------- layernorm ----------------------------------------------------
// MODE 0: fp32 out | MODE 1: bf16 hi/lo out | MODE 2: hi/lo out * sigmoid(res)
__device__ __forceinline__ float block_reduce_sum(float v, float* red){
    int tid = threadIdx.x;
    #pragma unroll
    for (int o=16;o;o>>=1) v += __shfl_xor_sync(0xffffffffu, v, o);
    if ((tid&31)==0) red[tid>>5] = v;
    __syncthreads();
    if (tid==0){
        float s = 0.f;
        #pragma unroll
        for (int i=0;i<8;i++) s += red[i];
        red[0] = s;
    }
    __syncthreads();
    float r = red[0];
    __syncthreads();
    return r;
}

template<int COLS, int MODE>
__global__ void __launch_bounds__(256) layernorm_k(
    const float* __restrict__ in, const float* __restrict__ gg,
    const float* __restrict__ bb, float* __restrict__ outf,
    __nv_bfloat16* __restrict__ oh, __nv_bfloat16* __restrict__ ol,
    const float* __restrict__ res, int resLd, int resOff)
{
    constexpr int VPT = COLS/256;
    __shared__ float red[8];
    int row = blockIdx.x;
    const float* x = in + (size_t)row*COLS;
    float v[VPT];
    float s = 0.f;
    #pragma unroll
    for (int i=0;i<VPT;i++){ v[i] = x[i*256 + threadIdx.x]; s += v[i]; }
    s = block_reduce_sum(s, red);
    float mu = s * (1.f/COLS);
    float q = 0.f;
    #pragma unroll
    for (int i=0;i<VPT;i++){ float c = v[i]-mu; q += c*c; }
    q = block_reduce_sum(q, red);
    float rstd = rsqrtf(q*(1.f/COLS) + 1e-5f);
    #pragma unroll
    for (int i=0;i<VPT;i++){
        int c = i*256 + threadIdx.x;
        float o = (v[i]-mu)*rstd*gg[c] + bb[c];
        if (MODE==2){
            float r = res[(size_t)row*resLd + resOff + c];
            o *= sigmoidf_(r);
        }
        size_t idx = (size_t)row*COLS + c;
        if (MODE==0){
            outf[idx] = o;
        } else {
            __nv_bfloat16 hh, ll;
            split_hl(o, hh, ll);
            oh[idx] = hh; ol[idx] = ll;
        }
    }
}

// ---------------- depthwise causal conv (K=4) + silu, float4-vectorized ------
template<bool IN_SILU>
__global__ void __launch_bounds__(256) dwconv4_k(
    const float* __restrict__ in, int ld,
    const float* __restrict__ w, const float* __restrict__ bias,
    float* __restrict__ out)
{
    const int ND4 = DI/4;   // 512
    int idx = blockIdx.x*256 + threadIdx.x;
    if (idx >= TOK*ND4) return;
    int d4 = idx & (ND4-1);
    int t  = idx >> 9;
    int s  = t & (SEQ-1);
    int d  = d4*4;
    float wf[16];
    *(float4*)&wf[0]  = *(const float4*)(w + (size_t)(d+0)*4);
    *(float4*)&wf[4]  = *(const float4*)(w + (size_t)(d+1)*4);
    *(float4*)&wf[8]  = *(const float4*)(w + (size_t)(d+2)*4);
    *(float4*)&wf[12] = *(const float4*)(w + (size_t)(d+3)*4);
    float4 acc4 = *(const float4*)(bias + d);
    float* accf = (float*)&acc4;
    #pragma unroll
    for (int k=0;k<Kc;k++){
        int tt = s - (Kc-1) + k;
        if (tt >= 0){
            float4 xv = *(const float4*)(in + (size_t)(t-(Kc-1)+k)*ld + d);
            float* xf = (float*)&xv;
            #pragma unroll
            for (int j=0;j<4;j++){
                float xvv = xf[j];
                if (IN_SILU) xvv = siluf_(xvv);
                accf[j] = fmaf(xvv, wf[j*4+k], accf[j]);
            }
        }
    }
    float4 o;
    o.x = siluf_(accf[0]); o.y = siluf_(accf[1]);
    o.z = siluf_(accf[2]); o.w = siluf_(accf[3]);
    *(float4*)(out + (size_t)t*DI + d) = o;
}

// ---------------- x_proj: proj[t, j] = sum_k xi[t,k] * W[j,k]  (J=33) ---------
__global__ void __launch_bounds__(256) xproj_k(
    const float* __restrict__ xi, const float* __restrict__ W,
    float* __restrict__ proj)
{
    __shared__ float sA[DI];
    int tok = blockIdx.x;
    const float* a = xi + (size_t)tok*DI;
    for (int i=threadIdx.x; i<DI; i+=256) sA[i] = a[i];
    __syncthreads();
    int w = threadIdx.x >> 5, lane = threadIdx.x & 31;
    for (int j = w; j < 33; j += 8){
        const float* Bw = W + (size_t)j*DI;
        float s = 0.f;
        for (int k = lane; k < DI; k += 32) s = fmaf(sA[k], Bw[k], s);
        #pragma unroll
        for (int o=16;o;o>>=1) s += __shfl_xor_sync(0xffffffffu, s, o);
        if (lane==0) proj[(size_t)tok*33 + j] = s;
    }
}

// ---------------- selective scan ---------------------------------------------
#define TCH 64
__global__ void __launch_bounds__(128) scan_k(
    const float* __restrict__ proj, const float* __restrict__ xi,
    const float* __restrict__ dtw, const float* __restrict__ dtb,
    const float* __restrict__ Dp, float* __restrict__ y)
{
    int b = blockIdx.y;
    int d = blockIdx.x*128 + threadIdx.x;
    float w_dt = dtw[d];
    float b_dt = dtb[d];
    float Dd   = Dp[d];
    float h[Nst];
    #pragma unroll
    for (int n=0;n<Nst;n++) h[n]=0.f;

    __shared__ float sp[TCH][36];
    const float* projB = proj + (size_t)b*SEQ*33;
    const float* xiB   = xi   + (size_t)b*SEQ*DI + d;
    float*       yB    = y    + (size_t)b*SEQ*DI + d;

    for (int t0=0; t0<SEQ; t0+=TCH){
        __syncthreads();
        for (int i=threadIdx.x; i<TCH*33; i+=128){
            int t = i/33, j = i%33;
            int slot = (j==0) ? 0 : (j+3);
            sp[t][slot] = projB[(size_t)(t0)*33 + i];
        }
        __syncthreads();
        for (int tt=0; tt<TCH; tt++){
            int t = t0+tt;
            const float* r = sp[tt];
            float z = fmaf(r[0], w_dt, b_dt);
            float dt = (z > 15.f) ? z : log1pf(__expf(z));
            float xv = xiB[(size_t)t*DI];
            float4 B0 = *(const float4*)&r[4];
            float4 B1 = *(const float4*)&r[8];
            float4 B2 = *(const float4*)&r[12];
            float4 B3 = *(const float4*)&r[16];
            float4 C0 = *(const float4*)&r[20];
            float4 C1 = *(const float4*)&r[24];
            float4 C2 = *(const float4*)&r[28];
            float4 C3 = *(const float4*)&r[32];
            float bArr[16] = {B0.x,B0.y,B0.z,B0.w,B1.x,B1.y,B1.z,B1.w,
                              B2.x,B2.y,B2.z,B2.w,B3.x,B3.y,B3.z,B3.w};
            float cArr[16] = {C0.x,C0.y,C0.z,C0.w,C1.x,C1.y,C1.z,C1.w,
                              C2.x,C2.y,C2.z,C2.w,C3.x,C3.y,C3.z,C3.w};
            float yv = 0.f;
            #pragma unroll
            for (int n=0;n<Nst;n++){
                float An = -(float)(n+1);
                float u = fmaf(h[n], An, xv * bArr[n]);
                h[n] = fmaf(dt, u, h[n]);
                yv = fmaf(h[n], cArr[n], yv);
            }
            yB[(size_t)t*DI] = fmaf(xv, Dd, yv);
        }
    }
}

// ---------------- host side ---------------------------------------------------
static void* sym_addr_(const void* symbol){
    void* p = nullptr;
    cudaGetSymbolAddress(&p, symbol);
    return p;
}

template<int EPI>
static void launch_gemm(const __nv_bfloat16* Ah, const __nv_bfloat16* Al,
                        const __nv_bfloat16* Bh, const __nv_bfloat16* Bl,
                        float* C, int M, int N, int K,
                        const float* bias, const float* R1,
                        __nv_bfloat16* Oh, __nv_bfloat16* Ol){
    cudaFuncSetAttribute(mma_gemm_nt<EPI>, cudaFuncAttributeMaxDynamicSharedMemorySize, GSM);
    dim3 grid(N/BN, M/BM);
    mma_gemm_nt<EPI><<<grid, 256, GSM>>>(Ah, Al, Bh, Bl, C, M, N, K, bias, R1, Oh, Ol);
}

static void cvt(const float* src, __nv_bfloat16* hi, __nv_bfloat16* lo, int n){
    cvt_hilo_k<<<(n/4 + 255)/256, 256>>>(src, hi, lo, n);
}

extern "C" void kernel_launch(void* const* d_in, const int* in_sizes, int n_in,
                              void* d_out, int out_size)
{
    const float* hidden   = (const float*)d_in[0];
    const float* in_ng    = (const float*)d_in[1];
    const float* in_nb    = (const float*)d_in[2];
    const float* ln_g     = (const float*)d_in[3];
    const float* ln_b     = (const float*)d_in[4];
    const float* in_proj  = (const float*)d_in[5];   // (L, 2*DI, H)
    const float* conv_w   = (const float*)d_in[6];   // (L, 2, DI, K)
    const float* conv_b   = (const float*)d_in[7];   // (L, 2, DI)
    const float* x_proj   = (const float*)d_in[8];   // (L, 33, DI)
    const float* dt_w     = (const float*)d_in[9];   // (L, DI, 1)
    const float* dt_b     = (const float*)d_in[10];  // (L, DI)
    const float* Dparam   = (const float*)d_in[11];  // (L, DI)
    const float* mln_g    = (const float*)d_in[12];
    const float* mln_b    = (const float*)d_in[13];
    const float* out_proj = (const float*)d_in[14];  // (L, H, DI)
    const float* op1_w    = (const float*)d_in[15];
    const float* op1_b    = (const float*)d_in[16];
    const float* op2_w    = (const float*)d_in[17];
    const float* op2_b    = (const float*)d_in[18];
    float* out = (float*)d_out;

    float* x   = (float*)sym_addr_(g_x);
    float* xr  = (float*)sym_addr_(g_xr);
    float* c1  = (float*)sym_addr_(g_c1);
    float* xi  = (float*)sym_addr_(g_xi);
    float* pj  = (float*)sym_addr_(g_proj);
    float* yb  = (float*)sym_addr_(g_y);
    __nv_bfloat16* wh = (__nv_bfloat16*)sym_addr_(g_wh);
    __nv_bfloat16* wl = (__nv_bfloat16*)sym_addr_(g_wl);
    __nv_bfloat16* ah = (__nv_bfloat16*)sym_addr_(g_ah);
    __nv_bfloat16* al = (__nv_bfloat16*)sym_addr_(g_al);
    __nv_bfloat16* bh = (__nv_bfloat16*)sym_addr_(g_bh);
    __nv_bfloat16* bl = (__nv_bfloat16*)sym_addr_(g_bl);

    // weight pre-conversion (once per launch)
    cvt(in_proj,  wh + WOFF_IP, wl + WOFF_IP, Ld*2*DI*Hd);
    cvt(out_proj, wh + WOFF_OP, wl + WOFF_OP, Ld*Hd*DI);
    cvt(op1_w,    wh + WOFF_M1, wl + WOFF_M1, Hd*Hd);
    cvt(op2_w,    wh + WOFF_M2, wl + WOFF_M2, Hd*Hd);

    // x = LN(hidden)  (fp32)
    layernorm_k<Hd,0><<<TOK,256>>>(hidden, in_ng, in_nb, x, nullptr, nullptr, nullptr, 0, 0);

    for (int l=0; l<Ld; l++){
        // xn -> hi/lo
        layernorm_k<Hd,1><<<TOK,256>>>(x, ln_g + l*Hd, ln_b + l*Hd,
                                       nullptr, ah, al, nullptr, 0, 0);
        // xr = xn @ in_proj_w[l]^T   (TOK x 4096)
        launch_gemm<0>(ah, al,
                       wh + WOFF_IP + (size_t)l*2*DI*Hd, wl + WOFF_IP + (size_t)l*2*DI*Hd,
                       xr, TOK, 2*DI, Hd, nullptr, nullptr, nullptr, nullptr);
        // conv1 -> c1 ; conv2 -> xi
        {
            int blocks = (TOK*(DI/4) + 255)/256;
            dwconv4_k<true><<<blocks,256>>>(
                xr, 2*DI,
                conv_w + (size_t)(l*2+0)*DI*Kc, conv_b + (size_t)(l*2+0)*DI, c1);
            dwconv4_k<false><<<blocks,256>>>(
                c1, DI,
                conv_w + (size_t)(l*2+1)*DI*Kc, conv_b + (size_t)(l*2+1)*DI, xi);
        }
        // proj = xi @ x_proj_w[l]^T  (TOK x 33)
        xproj_k<<<TOK,256>>>(xi, x_proj + (size_t)l*33*DI, pj);
        // scan -> y (+ xi * D fused)
        {
            dim3 grid(DI/128, BATCH);
            scan_k<<<grid,128>>>(pj, xi, dt_w + (size_t)l*DI, dt_b + (size_t)l*DI,
                                 Dparam + (size_t)l*DI, yb);
        }
        // y2 = LN_mamba(y) * sigmoid(res)  -> hi/lo
        layernorm_k<DI,2><<<TOK,256>>>(yb, mln_g + (size_t)l*DI, mln_b + (size_t)l*DI,
                                       nullptr, ah, al, xr, 2*DI, DI);
        // x = x + y2 @ out_proj_w[l]^T
        launch_gemm<2>(ah, al,
                       wh + WOFF_OP + (size_t)l*Hd*DI, wl + WOFF_OP + (size_t)l*Hd*DI,
                       x, TOK, Hd, DI, nullptr, x, nullptr, nullptr);
    }

    // MLP
    cvt(x, ah, al, TOK*Hd);
    launch_gemm<1>(ah, al, wh + WOFF_M1, wl + WOFF_M1,
                   nullptr, TOK, Hd, Hd, op1_b, nullptr, bh, bl);
    launch_gemm<3>(bh, bl, wh + WOFF_M2, wl + WOFF_M2,
                   out, TOK, Hd, Hd, op2_b, hidden, nullptr, nullptr);
}

// round 15
// speedup vs baseline: 1.5475x; 1.5475x over previous
#include <cuda_runtime.h>
#include <cuda_bf16.h>
#include <math.h>
#include <stdint.h>

// Problem constants
#define Hd 1024
#define Ld 4
#define DI 2048
#define Nst 16
#define Kc 4
#define BATCH 2
#define SEQ 1024
#define TOK (BATCH*SEQ)          // 2048 tokens

// ---------------- scratch buffers (device globals; no allocation) -------------
__device__ float g_x  [TOK*Hd];
__device__ float g_xr [TOK*2*DI];
__device__ float g_c1 [TOK*DI];
__device__ float g_xi [TOK*DI];
__device__ float g_proj[TOK*33];
__device__ float g_y  [TOK*DI];

// bf16 hi/lo operand buffers
#define WOFF_IP 0
#define WOFF_OP (Ld*2*DI*Hd)                    // 16777216
#define WOFF_M1 (WOFF_OP + Ld*Hd*DI)            // 25165824
#define WOFF_M2 (WOFF_M1 + Hd*Hd)               // 26214400
#define WTOT    (WOFF_M2 + Hd*Hd)               // 27262976
__device__ __nv_bfloat16 g_wh[WTOT];
__device__ __nv_bfloat16 g_wl[WTOT];
__device__ __nv_bfloat16 g_ah[TOK*DI];
__device__ __nv_bfloat16 g_al[TOK*DI];
__device__ __nv_bfloat16 g_bh[TOK*Hd];
__device__ __nv_bfloat16 g_bl[TOK*Hd];

// ---------------- helpers ----------------------------------------------------
__device__ __forceinline__ float sigmoidf_(float x){ return 1.f/(1.f+__expf(-x)); }
__device__ __forceinline__ float siluf_(float x){ return x * (1.f/(1.f+__expf(-x))); }
__device__ __forceinline__ float geluf_(float x){ return 0.5f*x*(1.f+erff(x*0.70710678118654752f)); }

__device__ __forceinline__ uint32_t smem_u32(const void* p){
    uint32_t a;
    asm("{ .reg .u64 t; cvta.to.shared.u64 t, %1; cvt.u32.u64 %0, t; }" : "=r"(a) : "l"(p));
    return a;
}
__device__ __forceinline__ void ldsm_x4(uint32_t* r, uint32_t addr){
    asm volatile("ldmatrix.sync.aligned.m8n8.x4.shared.b16 {%0,%1,%2,%3}, [%4];"
        : "=r"(r[0]), "=r"(r[1]), "=r"(r[2]), "=r"(r[3]) : "r"(addr));
}
__device__ __forceinline__ void ldsm_x2(uint32_t* r, uint32_t addr){
    asm volatile("ldmatrix.sync.aligned.m8n8.x2.shared.b16 {%0,%1}, [%2];"
        : "=r"(r[0]), "=r"(r[1]) : "r"(addr));
}
__device__ __forceinline__ void mma_bf16(float* c, const uint32_t* a, const uint32_t* b){
    asm volatile(
        "mma.sync.aligned.m16n8k16.row.col.f32.bf16.bf16.f32 "
        "{%0,%1,%2,%3}, {%4,%5,%6,%7}, {%8,%9}, {%0,%1,%2,%3};"
        : "+f"(c[0]), "+f"(c[1]), "+f"(c[2]), "+f"(c[3])
        : "r"(a[0]), "r"(a[1]), "r"(a[2]), "r"(a[3]), "r"(b[0]), "r"(b[1]));
}
__device__ __forceinline__ void cp16(uint32_t s, const void* g){
    asm volatile("cp.async.cg.shared.global [%0], [%1], 16;" :: "r"(s), "l"(g));
}
__device__ __forceinline__ void cp_commit(){
    asm volatile("cp.async.commit_group;" ::: "memory");
}
template<int N> __device__ __forceinline__ void cp_wait(){
    asm volatile("cp.async.wait_group %0;" :: "n"(N) : "memory");
}
__device__ __forceinline__ void split_hl(float v, __nv_bfloat16& h, __nv_bfloat16& l){
    h = __float2bfloat16(v);
    l = __float2bfloat16(v - __bfloat162float(h));
}

// ---------------- fp32 -> bf16 hi/lo conversion (4x float4 per thread) --------
__global__ void __launch_bounds__(256) cvt_hilo_k(
    const float* __restrict__ src, __nv_bfloat16* __restrict__ hi,
    __nv_bfloat16* __restrict__ lo, int n)
{
    int base = blockIdx.x*4096 + threadIdx.x*4;
    #pragma unroll
    for (int u=0; u<4; u++){
        int i = base + u*1024;
        if (i >= n) return;
        float4 v = *(const float4*)(src + i);
        __nv_bfloat16 h0,h1,h2,h3,l0,l1,l2,l3;
        split_hl(v.x,h0,l0); split_hl(v.y,h1,l1);
        split_hl(v.z,h2,l2); split_hl(v.w,h3,l3);
        __nv_bfloat162 hh0; hh0.x=h0; hh0.y=h1;
        __nv_bfloat162 hh1; hh1.x=h2; hh1.y=h3;
        __nv_bfloat162 ll0; ll0.x=l0; ll0.y=l1;
        __nv_bfloat162 ll1; ll1.x=l2; ll1.y=l3;
        *(uint2*)(hi+i) = make_uint2(*(uint32_t*)&hh0, *(uint32_t*)&hh1);
        *(uint2*)(lo+i) = make_uint2(*(uint32_t*)&ll0, *(uint32_t*)&ll1);
    }
}

// ---------------- tensor-core GEMM NT, bf16 hi/lo operands --------------------
// C[m,n] = sum_k A[m,k]*B[n,k]; operands pre-split hi/lo bf16, K-major rows.
#define BM 128
#define BN 128
#define GBK 32                 // bf16 K elems per chunk
#define GP 80                  // byte pitch per smem row (40 bf16)
#define GTILE (128*GP)         // 10240 B
#define ST_AHI 0
#define ST_ALO (1*GTILE)
#define ST_BHI (2*GTILE)
#define ST_BLO (3*GTILE)
#define GSTG (4*GTILE)         // 40960 B per stage
#define GSM  (2*GSTG)          // 81920 B  -> 2 CTAs/SM

// EPI: 0 none(fp32 C) | 1 gelu(acc+bias)->hi/lo | 2 acc+R1 (fp32) | 3 acc+bias+R1 (fp32)
template<int EPI>
__global__ void __launch_bounds__(256, 2) mma_gemm_nt(
    const __nv_bfloat16* __restrict__ Ahi, const __nv_bfloat16* __restrict__ Alo,
    const __nv_bfloat16* __restrict__ Bhi, const __nv_bfloat16* __restrict__ Blo,
    float* __restrict__ C, int M, int N, int K,
    const float* __restrict__ bias, const float* __restrict__ R1,
    __nv_bfloat16* __restrict__ Oh, __nv_bfloat16* __restrict__ Ol)
{
    extern __shared__ char smem[];
    const uint32_t smb = smem_u32(smem);
    const int tid  = threadIdx.x;
    const int wid  = tid >> 5;
    const int lane = tid & 31;
    const int bm = blockIdx.y * BM;
    const int bn = blockIdx.x * BN;
    const int warp_m = (wid >> 2) * 64;
    const int warp_n = (wid & 3) * 32;

    // cp.async mapping: row = tid/2, half = tid&1 (32B each)
    const int grow = tid >> 1;
    const int ghalf = tid & 1;
    const uint32_t soff = (uint32_t)grow*GP + (uint32_t)ghalf*32;
    const size_t aBase = (size_t)(bm + grow)*K + ghalf*16;
    const size_t bBase = (size_t)(bn + grow)*K + ghalf*16;

    // ldmatrix lane offsets (byte, within a tile)
    const int a_r  = ((lane >> 3) & 1)*8 + (lane & 7);
    const int a_k8 = (lane >> 4) * 8;
    const uint32_t a_lane_off = (uint32_t)(warp_m + a_r)*GP + (uint32_t)a_k8*2;
    const int l16  = lane & 15;
    const uint32_t b_lane_off = (uint32_t)(warp_n + (l16 & 7))*GP + (uint32_t)(l16 >> 3)*16;

    float acc[4][4][4];
    #pragma unroll
    for (int i=0;i<4;i++)
        #pragma unroll
        for (int j=0;j<4;j++)
            #pragma unroll
            for (int q=0;q<4;q++) acc[i][j][q]=0.f;

    const int NK = K / GBK;

    auto load_stage = [&](int s, int kc){
        uint32_t base = smb + s*GSTG;
        size_t ka = aBase + (size_t)kc*GBK;
        size_t kb = bBase + (size_t)kc*GBK;
        cp16(base+ST_AHI+soff,    Ahi+ka);  cp16(base+ST_AHI+soff+16, Ahi+ka+8);
        cp16(base+ST_ALO+soff,    Alo+ka);  cp16(base+ST_ALO+soff+16, Alo+ka+8);
        cp16(base+ST_BHI+soff,    Bhi+kb);  cp16(base+ST_BHI+soff+16, Bhi+kb+8);
        cp16(base+ST_BLO+soff,    Blo+kb);  cp16(base+ST_BLO+soff+16, Blo+kb+8);
        cp_commit();
    };
    auto compute_stage = [&](int s){
        uint32_t base = smb + s*GSTG;
        #pragma unroll
        for (int kk=0; kk<GBK; kk+=16){
            uint32_t ahi[4][4], alo[4][4], bhi[4][2], blo[4][2];
            #pragma unroll
            for (int tm=0; tm<4; tm++){
                uint32_t o = base + a_lane_off + (uint32_t)tm*16*GP + (uint32_t)kk*2;
                ldsm_x4(ahi[tm], o + ST_AHI);
                ldsm_x4(alo[tm], o + ST_ALO);
            }
            #pragma unroll
            for (int tn=0; tn<4; tn++){
                uint32_t o = base + b_lane_off + (uint32_t)tn*8*GP + (uint32_t)kk*2;
                ldsm_x2(bhi[tn], o + ST_BHI);
                ldsm_x2(blo[tn], o + ST_BLO);
            }
            #pragma unroll
            for (int tm=0; tm<4; tm++)
                #pragma unroll
                for (int tn=0; tn<4; tn++){
                    mma_bf16(acc[tm][tn], ahi[tm], bhi[tn]);
                    mma_bf16(acc[tm][tn], ahi[tm], blo[tn]);
                    mma_bf16(acc[tm][tn], alo[tm], bhi[tn]);
                }
        }
    };

    // prologue: 2 stages in flight
    load_stage(0, 0);
    load_stage(1, 1);

    for (int kc=0; kc<NK; kc++){
        if (kc >= NK-2) cp_wait<0>(); else cp_wait<1>();
        __syncthreads();
        compute_stage(kc & 1);
        __syncthreads();
        if (kc+2 < NK) load_stage(kc & 1, kc+2);
    }

    // epilogue
    const int er = lane >> 2;
    const int ec = (lane & 3) * 2;
    #pragma unroll
    for (int tm=0; tm<4; tm++){
        #pragma unroll
        for (int tn=0; tn<4; tn++){
            int m0 = bm + warp_m + tm*16 + er;
            int n0 = bn + warp_n + tn*8 + ec;
            float* cr = acc[tm][tn];
            #pragma unroll
            for (int h=0; h<2; h++){
                int m = m0 + h*8;
                size_t idx = (size_t)m*N + n0;
                float v0 = cr[h*2+0], v1 = cr[h*2+1];
                if (EPI==1){
                    v0 = geluf_(v0 + bias[n0]); v1 = geluf_(v1 + bias[n0+1]);
                    __nv_bfloat16 h0,h1,l0,l1;
                    split_hl(v0,h0,l0); split_hl(v1,h1,l1);
                    __nv_bfloat162 hh; hh.x=h0; hh.y=h1;
                    __nv_bfloat162 ll; ll.x=l0; ll.y=l1;
                    *(uint32_t*)&Oh[idx] = *(uint32_t*)&hh;
                    *(uint32_t*)&Ol[idx] = *(uint32_t*)&ll;
                } else {
                    if (EPI==2){ v0 += R1[idx]; v1 += R1[idx+1]; }
                    else if (EPI==3){ v0 += bias[n0] + R1[idx]; v1 += bias[n0+1] + R1[idx+1]; }
                    float2 o; o.x=v0; o.y=v1;
                    *(float2*)&C[idx] = o;
                }
            }
        }
    }
}

// ---------------- layernorm ----------------------------------------------------
__device__ __forceinline__ float block_reduce_sum(float v, float* red){
    int tid = threadIdx.x;
    #pragma unroll
    for (int o=16;o;o>>=1) v += __shfl_xor_sync(0xffffffffu, v, o);
    if ((tid&31)==0) red[tid>>5] = v;
    __syncthreads();
    if (tid==0){
        float s = 0.f;
        #pragma unroll
        for (int i=0;i<8;i++) s += red[i];
        red[0] = s;
    }
    __syncthreads();
    float r = red[0];
    __syncthreads();
    return r;
}

// MODE 0: fp32 out | MODE 1: bf16 hi/lo out | MODE 2: hi/lo out * sigmoid(res)
template<int COLS, int MODE>
__global__ void __launch_bounds__(256) layernorm_k(
    const float* __restrict__ in, const float* __restrict__ gg,
    const float* __restrict__ bb, float* __restrict__ outf,
    __nv_bfloat16* __restrict__ oh, __nv_bfloat16* __restrict__ ol,
    const float* __restrict__ res, int resLd, int resOff)
{
    constexpr int VPT = COLS/256;
    __shared__ float red[8];
    int row = blockIdx.x;
    const float* x = in + (size_t)row*COLS;
    float v[VPT];
    float s = 0.f;
    #pragma unroll
    for (int i=0;i<VPT;i++){ v[i] = x[i*256 + threadIdx.x]; s += v[i]; }
    s = block_reduce_sum(s, red);
    float mu = s * (1.f/COLS);
    float q = 0.f;
    #pragma unroll
    for (int i=0;i<VPT;i++){ float c = v[i]-mu; q += c*c; }
    q = block_reduce_sum(q, red);
    float rstd = rsqrtf(q*(1.f/COLS) + 1e-5f);
    #pragma unroll
    for (int i=0;i<VPT;i++){
        int c = i*256 + threadIdx.x;
        float o = (v[i]-mu)*rstd*gg[c] + bb[c];
        if (MODE==2){
            float r = res[(size_t)row*resLd + resOff + c];
            o *= sigmoidf_(r);
        }
        size_t idx = (size_t)row*COLS + c;
        if (MODE==0){
            outf[idx] = o;
        } else {
            __nv_bfloat16 hh, ll;
            split_hl(o, hh, ll);
            oh[idx] = hh; ol[idx] = ll;
        }
    }
}

// ---------------- depthwise causal conv (K=4) + silu, float4-vectorized ------
template<bool IN_SILU>
__global__ void __launch_bounds__(256) dwconv4_k(
    const float* __restrict__ in, int ld,
    const float* __restrict__ w, const float* __restrict__ bias,
    float* __restrict__ out)
{
    const int ND4 = DI/4;   // 512
    int idx = blockIdx.x*256 + threadIdx.x;
    if (idx >= TOK*ND4) return;
    int d4 = idx & (ND4-1);
    int t  = idx >> 9;
    int s  = t & (SEQ-1);
    int d  = d4*4;
    float wf[16];
    *(float4*)&wf[0]  = *(const float4*)(w + (size_t)(d+0)*4);
    *(float4*)&wf[4]  = *(const float4*)(w + (size_t)(d+1)*4);
    *(float4*)&wf[8]  = *(const float4*)(w + (size_t)(d+2)*4);
    *(float4*)&wf[12] = *(const float4*)(w + (size_t)(d+3)*4);
    float4 acc4 = *(const float4*)(bias + d);
    float* accf = (float*)&acc4;
    #pragma unroll
    for (int k=0;k<Kc;k++){
        int tt = s - (Kc-1) + k;
        if (tt >= 0){
            float4 xv = *(const float4*)(in + (size_t)(t-(Kc-1)+k)*ld + d);
            float* xf = (float*)&xv;
            #pragma unroll
            for (int j=0;j<4;j++){
                float xvv = xf[j];
                if (IN_SILU) xvv = siluf_(xvv);
                accf[j] = fmaf(xvv, wf[j*4+k], accf[j]);
            }
        }
    }
    float4 o;
    o.x = siluf_(accf[0]); o.y = siluf_(accf[1]);
    o.z = siluf_(accf[2]); o.w = siluf_(accf[3]);
    *(float4*)(out + (size_t)t*DI + d) = o;
}

// ---------------- x_proj: proj[t, j] = sum_k xi[t,k] * W[j,k]  (J=33) ---------
__global__ void __launch_bounds__(256) xproj_k(
    const float* __restrict__ xi, const float* __restrict__ W,
    float* __restrict__ proj)
{
    __shared__ float sA[DI];
    int tok = blockIdx.x;
    const float* a = xi + (size_t)tok*DI;
    for (int i=threadIdx.x; i<DI; i+=256) sA[i] = a[i];
    __syncthreads();
    int w = threadIdx.x >> 5, lane = threadIdx.x & 31;
    for (int j = w; j < 33; j += 8){
        const float* Bw = W + (size_t)j*DI;
        float s = 0.f;
        for (int k = lane; k < DI; k += 32) s = fmaf(sA[k], Bw[k], s);
        #pragma unroll
        for (int o=16;o;o>>=1) s += __shfl_xor_sync(0xffffffffu, s, o);
        if (lane==0) proj[(size_t)tok*33 + j] = s;
    }
}

// ---------------- selective scan ---------------------------------------------
#define TCH 64
__global__ void __launch_bounds__(128) scan_k(
    const float* __restrict__ proj, const float* __restrict__ xi,
    const float* __restrict__ dtw, const float* __restrict__ dtb,
    const float* __restrict__ Dp, float* __restrict__ y)
{
    int b = blockIdx.y;
    int d = blockIdx.x*128 + threadIdx.x;
    float w_dt = dtw[d];
    float b_dt = dtb[d];
    float Dd   = Dp[d];
    float h[Nst];
    #pragma unroll
    for (int n=0;n<Nst;n++) h[n]=0.f;

    __shared__ float sp[TCH][36];
    const float* projB = proj + (size_t)b*SEQ*33;
    const float* xiB   = xi   + (size_t)b*SEQ*DI + d;
    float*       yB    = y    + (size_t)b*SEQ*DI + d;

    for (int t0=0; t0<SEQ; t0+=TCH){
        __syncthreads();
        for (int i=threadIdx.x; i<TCH*33; i+=128){
            int t = i/33, j = i%33;
            int slot = (j==0) ? 0 : (j+3);
            sp[t][slot] = projB[(size_t)(t0)*33 + i];
        }
        __syncthreads();
        for (int tt=0; tt<TCH; tt++){
            int t = t0+tt;
            const float* r = sp[tt];
            float z = fmaf(r[0], w_dt, b_dt);
            float dt = (z > 15.f) ? z : log1pf(__expf(z));
            float xv = xiB[(size_t)t*DI];
            float4 B0 = *(const float4*)&r[4];
            float4 B1 = *(const float4*)&r[8];
            float4 B2 = *(const float4*)&r[12];
            float4 B3 = *(const float4*)&r[16];
            float4 C0 = *(const float4*)&r[20];
            float4 C1 = *(const float4*)&r[24];
            float4 C2 = *(const float4*)&r[28];
            float4 C3 = *(const float4*)&r[32];
            float bArr[16] = {B0.x,B0.y,B0.z,B0.w,B1.x,B1.y,B1.z,B1.w,
                              B2.x,B2.y,B2.z,B2.w,B3.x,B3.y,B3.z,B3.w};
            float cArr[16] = {C0.x,C0.y,C0.z,C0.w,C1.x,C1.y,C1.z,C1.w,
                              C2.x,C2.y,C2.z,C2.w,C3.x,C3.y,C3.z,C3.w};
            float yv = 0.f;
            #pragma unroll
            for (int n=0;n<Nst;n++){
                float An = -(float)(n+1);
                float u = fmaf(h[n], An, xv * bArr[n]);
                h[n] = fmaf(dt, u, h[n]);
                yv = fmaf(h[n], cArr[n], yv);
            }
            yB[(size_t)t*DI] = fmaf(xv, Dd, yv);
        }
    }
}

// ---------------- host side ---------------------------------------------------
static void* sym_addr_(const void* symbol){
    void* p = nullptr;
    cudaGetSymbolAddress(&p, symbol);
    return p;
}

template<int EPI>
static void launch_gemm(const __nv_bfloat16* Ah, const __nv_bfloat16* Al,
                        const __nv_bfloat16* Bh, const __nv_bfloat16* Bl,
                        float* C, int M, int N, int K,
                        const float* bias, const float* R1,
                        __nv_bfloat16* Oh, __nv_bfloat16* Ol){
    cudaFuncSetAttribute(mma_gemm_nt<EPI>, cudaFuncAttributeMaxDynamicSharedMemorySize, GSM);
    dim3 grid(N/BN, M/BM);
    mma_gemm_nt<EPI><<<grid, 256, GSM>>>(Ah, Al, Bh, Bl, C, M, N, K, bias, R1, Oh, Ol);
}

static void cvt(const float* src, __nv_bfloat16* hi, __nv_bfloat16* lo, int n){
    cvt_hilo_k<<<(n + 4095)/4096, 256>>>(src, hi, lo, n);
}

extern "C" void kernel_launch(void* const* d_in, const int* in_sizes, int n_in,
                              void* d_out, int out_size)
{
    const float* hidden   = (const float*)d_in[0];
    const float* in_ng    = (const float*)d_in[1];
    const float* in_nb    = (const float*)d_in[2];
    const float* ln_g     = (const float*)d_in[3];
    const float* ln_b     = (const float*)d_in[4];
    const float* in_proj  = (const float*)d_in[5];   // (L, 2*DI, H)
    const float* conv_w   = (const float*)d_in[6];   // (L, 2, DI, K)
    const float* conv_b   = (const float*)d_in[7];   // (L, 2, DI)
    const float* x_proj   = (const float*)d_in[8];   // (L, 33, DI)
    const float* dt_w     = (const float*)d_in[9];   // (L, DI, 1)
    const float* dt_b     = (const float*)d_in[10];  // (L, DI)
    const float* Dparam   = (const float*)d_in[11];  // (L, DI)
    const float* mln_g    = (const float*)d_in[12];
    const float* mln_b    = (const float*)d_in[13];
    const float* out_proj = (const float*)d_in[14];  // (L, H, DI)
    const float* op1_w    = (const float*)d_in[15];
    const float* op1_b    = (const float*)d_in[16];
    const float* op2_w    = (const float*)d_in[17];
    const float* op2_b    = (const float*)d_in[18];
    float* out = (float*)d_out;

    float* x   = (float*)sym_addr_(g_x);
    float* xr  = (float*)sym_addr_(g_xr);
    float* c1  = (float*)sym_addr_(g_c1);
    float* xi  = (float*)sym_addr_(g_xi);
    float* pj  = (float*)sym_addr_(g_proj);
    float* yb  = (float*)sym_addr_(g_y);
    __nv_bfloat16* wh = (__nv_bfloat16*)sym_addr_(g_wh);
    __nv_bfloat16* wl = (__nv_bfloat16*)sym_addr_(g_wl);
    __nv_bfloat16* ah = (__nv_bfloat16*)sym_addr_(g_ah);
    __nv_bfloat16* al = (__nv_bfloat16*)sym_addr_(g_al);
    __nv_bfloat16* bh = (__nv_bfloat16*)sym_addr_(g_bh);
    __nv_bfloat16* bl = (__nv_bfloat16*)sym_addr_(g_bl);

    // weight pre-conversion (once per launch)
    cvt(in_proj,  wh + WOFF_IP, wl + WOFF_IP, Ld*2*DI*Hd);
    cvt(out_proj, wh + WOFF_OP, wl + WOFF_OP, Ld*Hd*DI);
    cvt(op1_w,    wh + WOFF_M1, wl + WOFF_M1, Hd*Hd);
    cvt(op2_w,    wh + WOFF_M2, wl + WOFF_M2, Hd*Hd);

    // x = LN(hidden)  (fp32)
    layernorm_k<Hd,0><<<TOK,256>>>(hidden, in_ng, in_nb, x, nullptr, nullptr, nullptr, 0, 0);

    for (int l=0; l<Ld; l++){
        // xn -> hi/lo
        layernorm_k<Hd,1><<<TOK,256>>>(x, ln_g + l*Hd, ln_b + l*Hd,
                                       nullptr, ah, al, nullptr, 0, 0);
        // xr = xn @ in_proj_w[l]^T   (TOK x 4096)
        launch_gemm<0>(ah, al,
                       wh + WOFF_IP + (size_t)l*2*DI*Hd, wl + WOFF_IP + (size_t)l*2*DI*Hd,
                       xr, TOK, 2*DI, Hd, nullptr, nullptr, nullptr, nullptr);
        // conv1 -> c1 ; conv2 -> xi
        {
            int blocks = (TOK*(DI/4) + 255)/256;
            dwconv4_k<true><<<blocks,256>>>(
                xr, 2*DI,
                conv_w + (size_t)(l*2+0)*DI*Kc, conv_b + (size_t)(l*2+0)*DI, c1);
            dwconv4_k<false><<<blocks,256>>>(
                c1, DI,
                conv_w + (size_t)(l*2+1)*DI*Kc, conv_b + (size_t)(l*2+1)*DI, xi);
        }
        // proj = xi @ x_proj_w[l]^T  (TOK x 33)
        xproj_k<<<TOK,256>>>(xi, x_proj + (size_t)l*33*DI, pj);
        // scan -> y (+ xi * D fused)
        {
            dim3 grid(DI/128, BATCH);
            scan_k<<<grid,128>>>(pj, xi, dt_w + (size_t)l*DI, dt_b + (size_t)l*DI,
                                 Dparam + (size_t)l*DI, yb);
        }
        // y2 = LN_mamba(y) * sigmoid(res)  -> hi/lo
        layernorm_k<DI,2><<<TOK,256>>>(yb, mln_g + (size_t)l*DI, mln_b + (size_t)l*DI,
                                       nullptr, ah, al, xr, 2*DI, DI);
        // x = x + y2 @ out_proj_w[l]^T
        launch_gemm<2>(ah, al,
                       wh + WOFF_OP + (size_t)l*Hd*DI, wl + WOFF_OP + (size_t)l*Hd*DI,
                       x, TOK, Hd, DI, nullptr, x, nullptr, nullptr);
    }

    // MLP
    cvt(x, ah, al, TOK*Hd);
    launch_gemm<1>(ah, al, wh + WOFF_M1, wl + WOFF_M1,
                   nullptr, TOK, Hd, Hd, op1_b, nullptr, bh, bl);
    launch_gemm<3>(bh, bl, wh + WOFF_M2, wl + WOFF_M2,
                   out, TOK, Hd, Hd, op2_b, hidden, nullptr, nullptr);
}

// round 16
// speedup vs baseline: 1.8688x; 1.2076x over previous
#include <cuda_runtime.h>
#include <cuda_bf16.h>
#include <math.h>
#include <stdint.h>

// Problem constants
#define Hd 1024
#define Ld 4
#define DI 2048
#define Nst 16
#define Kc 4
#define BATCH 2
#define SEQ 1024
#define TOK (BATCH*SEQ)          // 2048 tokens

// ---------------- scratch buffers (device globals; no allocation) -------------
__device__ float g_x  [TOK*Hd];
__device__ float g_xr [TOK*2*DI];
__device__ float g_c1 [TOK*DI];
__device__ float g_xi [TOK*DI];
__device__ float g_proj[TOK*33];
__device__ float g_y  [TOK*DI];

// bf16 hi/lo operand buffers
#define WOFF_IP 0
#define WOFF_OP (Ld*2*DI*Hd)                    // 16777216
#define WOFF_M1 (WOFF_OP + Ld*Hd*DI)            // 25165824
#define WOFF_M2 (WOFF_M1 + Hd*Hd)               // 26214400
#define WTOT    (WOFF_M2 + Hd*Hd)               // 27262976
__device__ __nv_bfloat16 g_wh[WTOT];
__device__ __nv_bfloat16 g_wl[WTOT];
__device__ __nv_bfloat16 g_ah[TOK*DI];
__device__ __nv_bfloat16 g_al[TOK*DI];
__device__ __nv_bfloat16 g_bh[TOK*Hd];
__device__ __nv_bfloat16 g_bl[TOK*Hd];

// ---------------- helpers ----------------------------------------------------
__device__ __forceinline__ float sigmoidf_(float x){ return __fdividef(1.f, 1.f+__expf(-x)); }
__device__ __forceinline__ float siluf_(float x){ return x * __fdividef(1.f, 1.f+__expf(-x)); }
__device__ __forceinline__ float geluf_(float x){ return 0.5f*x*(1.f+erff(x*0.70710678118654752f)); }

__device__ __forceinline__ uint32_t smem_u32(const void* p){
    uint32_t a;
    asm("{ .reg .u64 t; cvta.to.shared.u64 t, %1; cvt.u32.u64 %0, t; }" : "=r"(a) : "l"(p));
    return a;
}
__device__ __forceinline__ void ldsm_x4(uint32_t* r, uint32_t addr){
    asm volatile("ldmatrix.sync.aligned.m8n8.x4.shared.b16 {%0,%1,%2,%3}, [%4];"
        : "=r"(r[0]), "=r"(r[1]), "=r"(r[2]), "=r"(r[3]) : "r"(addr));
}
__device__ __forceinline__ void ldsm_x2(uint32_t* r, uint32_t addr){
    asm volatile("ldmatrix.sync.aligned.m8n8.x2.shared.b16 {%0,%1}, [%2];"
        : "=r"(r[0]), "=r"(r[1]) : "r"(addr));
}
__device__ __forceinline__ void mma_bf16(float* c, const uint32_t* a, const uint32_t* b){
    asm volatile(
        "mma.sync.aligned.m16n8k16.row.col.f32.bf16.bf16.f32 "
        "{%0,%1,%2,%3}, {%4,%5,%6,%7}, {%8,%9}, {%0,%1,%2,%3};"
        : "+f"(c[0]), "+f"(c[1]), "+f"(c[2]), "+f"(c[3])
        : "r"(a[0]), "r"(a[1]), "r"(a[2]), "r"(a[3]), "r"(b[0]), "r"(b[1]));
}
__device__ __forceinline__ void cp16(uint32_t s, const void* g){
    asm volatile("cp.async.cg.shared.global [%0], [%1], 16;" :: "r"(s), "l"(g));
}
__device__ __forceinline__ void cp_commit(){
    asm volatile("cp.async.commit_group;" ::: "memory");
}
template<int N> __device__ __forceinline__ void cp_wait(){
    asm volatile("cp.async.wait_group %0;" :: "n"(N) : "memory");
}
__device__ __forceinline__ void split_hl(float v, __nv_bfloat16& h, __nv_bfloat16& l){
    h = __float2bfloat16(v);
    l = __float2bfloat16(v - __bfloat162float(h));
}
__device__ __forceinline__ uint32_t pack_bf2(float a, float b){
    __nv_bfloat162 p; p.x = __float2bfloat16(a); p.y = __float2bfloat16(b);
    return *(uint32_t*)&p;
}

// ---------------- fp32 -> bf16 hi/lo conversion (8 floats/thread, 16B stores) -
__global__ void __launch_bounds__(256) cvt_hilo_k(
    const float4* __restrict__ src, uint4* __restrict__ hi,
    uint4* __restrict__ lo, int n8)
{
    int i = blockIdx.x*256 + threadIdx.x;
    if (i >= n8) return;
    float4 v0 = src[2*i], v1 = src[2*i+1];
    float f[8] = {v0.x,v0.y,v0.z,v0.w, v1.x,v1.y,v1.z,v1.w};
    uint32_t hw[4], lw[4];
    #pragma unroll
    for (int q=0;q<4;q++){
        __nv_bfloat16 h0,h1,l0,l1;
        split_hl(f[2*q],h0,l0); split_hl(f[2*q+1],h1,l1);
        __nv_bfloat162 hh; hh.x=h0; hh.y=h1;
        __nv_bfloat162 ll; ll.x=l0; ll.y=l1;
        hw[q]=*(uint32_t*)&hh; lw[q]=*(uint32_t*)&ll;
    }
    hi[i] = make_uint4(hw[0],hw[1],hw[2],hw[3]);
    lo[i] = make_uint4(lw[0],lw[1],lw[2],lw[3]);
}

// ---------------- tensor-core GEMM NT, bf16 hi/lo operands --------------------
#define BM 128
#define BN 128
#define GBK 32
#define GP 80
#define GTILE (128*GP)
#define ST_AHI 0
#define ST_ALO (1*GTILE)
#define ST_BHI (2*GTILE)
#define ST_BLO (3*GTILE)
#define GSTG (4*GTILE)
#define GSM  (2*GSTG)          // 81920 B -> 2 CTAs/SM

// EPI: 0 none(fp32) | 1 gelu(acc+bias)->hi/lo | 2 acc+R1 fp32 | 3 acc+bias+R1 fp32 | 4 acc+R1 -> fp32 + hi/lo
template<int EPI>
__global__ void __launch_bounds__(256, 2) mma_gemm_nt(
    const __nv_bfloat16* __restrict__ Ahi, const __nv_bfloat16* __restrict__ Alo,
    const __nv_bfloat16* __restrict__ Bhi, const __nv_bfloat16* __restrict__ Blo,
    float* __restrict__ C, int M, int N, int K,
    const float* __restrict__ bias, const float* __restrict__ R1,
    __nv_bfloat16* __restrict__ Oh, __nv_bfloat16* __restrict__ Ol)
{
    extern __shared__ char smem[];
    const uint32_t smb = smem_u32(smem);
    const int tid  = threadIdx.x;
    const int wid  = tid >> 5;
    const int lane = tid & 31;
    const int bm = blockIdx.y * BM;
    const int bn = blockIdx.x * BN;
    const int warp_m = (wid >> 2) * 64;
    const int warp_n = (wid & 3) * 32;

    const int grow = tid >> 1;
    const int ghalf = tid & 1;
    const uint32_t soff = (uint32_t)grow*GP + (uint32_t)ghalf*32;
    const size_t aBase = (size_t)(bm + grow)*K + ghalf*16;
    const size_t bBase = (size_t)(bn + grow)*K + ghalf*16;

    const int a_r  = ((lane >> 3) & 1)*8 + (lane & 7);
    const int a_k8 = (lane >> 4) * 8;
    const uint32_t a_lane_off = (uint32_t)(warp_m + a_r)*GP + (uint32_t)a_k8*2;
    const int l16  = lane & 15;
    const uint32_t b_lane_off = (uint32_t)(warp_n + (l16 & 7))*GP + (uint32_t)(l16 >> 3)*16;

    float acc[4][4][4];
    #pragma unroll
    for (int i=0;i<4;i++)
        #pragma unroll
        for (int j=0;j<4;j++)
            #pragma unroll
            for (int q=0;q<4;q++) acc[i][j][q]=0.f;

    const int NK = K / GBK;

    auto load_stage = [&](int s, int kc){
        uint32_t base = smb + s*GSTG;
        size_t ka = aBase + (size_t)kc*GBK;
        size_t kb = bBase + (size_t)kc*GBK;
        cp16(base+ST_AHI+soff,    Ahi+ka);  cp16(base+ST_AHI+soff+16, Ahi+ka+8);
        cp16(base+ST_ALO+soff,    Alo+ka);  cp16(base+ST_ALO+soff+16, Alo+ka+8);
        cp16(base+ST_BHI+soff,    Bhi+kb);  cp16(base+ST_BHI+soff+16, Bhi+kb+8);
        cp16(base+ST_BLO+soff,    Blo+kb);  cp16(base+ST_BLO+soff+16, Blo+kb+8);
        cp_commit();
    };
    auto compute_stage = [&](int s){
        uint32_t base = smb + s*GSTG;
        #pragma unroll
        for (int kk=0; kk<GBK; kk+=16){
            uint32_t ahi[4][4], alo[4][4], bhi[4][2], blo[4][2];
            #pragma unroll
            for (int tm=0; tm<4; tm++){
                uint32_t o = base + a_lane_off + (uint32_t)tm*16*GP + (uint32_t)kk*2;
                ldsm_x4(ahi[tm], o + ST_AHI);
                ldsm_x4(alo[tm], o + ST_ALO);
            }
            #pragma unroll
            for (int tn=0; tn<4; tn++){
                uint32_t o = base + b_lane_off + (uint32_t)tn*8*GP + (uint32_t)kk*2;
                ldsm_x2(bhi[tn], o + ST_BHI);
                ldsm_x2(blo[tn], o + ST_BLO);
            }
            #pragma unroll
            for (int tm=0; tm<4; tm++)
                #pragma unroll
                for (int tn=0; tn<4; tn++){
                    mma_bf16(acc[tm][tn], ahi[tm], bhi[tn]);
                    mma_bf16(acc[tm][tn], ahi[tm], blo[tn]);
                    mma_bf16(acc[tm][tn], alo[tm], bhi[tn]);
                }
        }
    };

    load_stage(0, 0);
    load_stage(1, 1);

    for (int kc=0; kc<NK; kc++){
        if (kc >= NK-2) cp_wait<0>(); else cp_wait<1>();
        __syncthreads();
        compute_stage(kc & 1);
        __syncthreads();
        if (kc+2 < NK) load_stage(kc & 1, kc+2);
    }

    // epilogue
    const int er = lane >> 2;
    const int ec = (lane & 3) * 2;
    #pragma unroll
    for (int tm=0; tm<4; tm++){
        #pragma unroll
        for (int tn=0; tn<4; tn++){
            int m0 = bm + warp_m + tm*16 + er;
            int n0 = bn + warp_n + tn*8 + ec;
            float* cr = acc[tm][tn];
            #pragma unroll
            for (int h=0; h<2; h++){
                int m = m0 + h*8;
                size_t idx = (size_t)m*N + n0;
                float v0 = cr[h*2+0], v1 = cr[h*2+1];
                if (EPI==1){
                    v0 = geluf_(v0 + bias[n0]); v1 = geluf_(v1 + bias[n0+1]);
                    __nv_bfloat16 h0,h1,l0,l1;
                    split_hl(v0,h0,l0); split_hl(v1,h1,l1);
                    __nv_bfloat162 hh; hh.x=h0; hh.y=h1;
                    __nv_bfloat162 ll; ll.x=l0; ll.y=l1;
                    *(uint32_t*)&Oh[idx] = *(uint32_t*)&hh;
                    *(uint32_t*)&Ol[idx] = *(uint32_t*)&ll;
                } else if (EPI==4){
                    v0 += R1[idx]; v1 += R1[idx+1];
                    __nv_bfloat16 h0,h1,l0,l1;
                    split_hl(v0,h0,l0); split_hl(v1,h1,l1);
                    __nv_bfloat162 hh; hh.x=h0; hh.y=h1;
                    __nv_bfloat162 ll; ll.x=l0; ll.y=l1;
                    *(uint32_t*)&Oh[idx] = *(uint32_t*)&hh;
                    *(uint32_t*)&Ol[idx] = *(uint32_t*)&ll;
                } else {
                    if (EPI==2){ v0 += R1[idx]; v1 += R1[idx+1]; }
                    else if (EPI==3){ v0 += bias[n0] + R1[idx]; v1 += bias[n0+1] + R1[idx+1]; }
                    float2 o; o.x=v0; o.y=v1;
                    *(float2*)&C[idx] = o;
                }
            }
        }
    }
}

// ---------------- layernorm (float4 loads, bf16x2 paired stores) --------------
__device__ __forceinline__ float block_reduce_sum(float v, float* red){
    int tid = threadIdx.x;
    #pragma unroll
    for (int o=16;o;o>>=1) v += __shfl_xor_sync(0xffffffffu, v, o);
    if ((tid&31)==0) red[tid>>5] = v;
    __syncthreads();
    if (tid==0){
        float s = 0.f;
        #pragma unroll
        for (int i=0;i<8;i++) s += red[i];
        red[0] = s;
    }
    __syncthreads();
    float r = red[0];
    __syncthreads();
    return r;
}

// MODE 0: fp32 out | MODE 1: bf16 hi/lo out | MODE 2: hi/lo out * sigmoid(res)
template<int COLS, int MODE>
__global__ void __launch_bounds__(256) layernorm_k(
    const float* __restrict__ in, const float* __restrict__ gg,
    const float* __restrict__ bb, float* __restrict__ outf,
    __nv_bfloat16* __restrict__ oh, __nv_bfloat16* __restrict__ ol,
    const float* __restrict__ res, int resLd, int resOff)
{
    constexpr int V4 = COLS/1024;      // float4s per thread
    __shared__ float red[8];
    int row = blockIdx.x;
    const float* x = in + (size_t)row*COLS;
    float4 v[V4];
    float s = 0.f;
    #pragma unroll
    for (int i=0;i<V4;i++){
        v[i] = *(const float4*)(x + i*1024 + threadIdx.x*4);
        s += v[i].x + v[i].y + v[i].z + v[i].w;
    }
    s = block_reduce_sum(s, red);
    float mu = s * (1.f/COLS);
    float q = 0.f;
    #pragma unroll
    for (int i=0;i<V4;i++){
        float a=v[i].x-mu, b=v[i].y-mu, c=v[i].z-mu, d=v[i].w-mu;
        q += a*a + b*b + c*c + d*d;
    }
    q = block_reduce_sum(q, red);
    float rstd = rsqrtf(q*(1.f/COLS) + 1e-5f);
    #pragma unroll
    for (int i=0;i<V4;i++){
        int c0 = i*1024 + threadIdx.x*4;
        float4 gv = *(const float4*)(gg + c0);
        float4 bv = *(const float4*)(bb + c0);
        float o0 = (v[i].x-mu)*rstd*gv.x + bv.x;
        float o1 = (v[i].y-mu)*rstd*gv.y + bv.y;
        float o2 = (v[i].z-mu)*rstd*gv.z + bv.z;
        float o3 = (v[i].w-mu)*rstd*gv.w + bv.w;
        if (MODE==2){
            float4 rv = *(const float4*)(res + (size_t)row*resLd + resOff + c0);
            o0 *= sigmoidf_(rv.x); o1 *= sigmoidf_(rv.y);
            o2 *= sigmoidf_(rv.z); o3 *= sigmoidf_(rv.w);
        }
        size_t idx = (size_t)row*COLS + c0;
        if (MODE==0){
            float4 o; o.x=o0;o.y=o1;o.z=o2;o.w=o3;
            *(float4*)(outf + idx) = o;
        } else {
            __nv_bfloat16 h0,h1,h2,h3,l0,l1,l2,l3;
            split_hl(o0,h0,l0); split_hl(o1,h1,l1);
            split_hl(o2,h2,l2); split_hl(o3,h3,l3);
            __nv_bfloat162 ha; ha.x=h0; ha.y=h1;
            __nv_bfloat162 hb; hb.x=h2; hb.y=h3;
            __nv_bfloat162 la; la.x=l0; la.y=l1;
            __nv_bfloat162 lb; lb.x=l2; lb.y=l3;
            *(uint2*)(oh + idx) = make_uint2(*(uint32_t*)&ha, *(uint32_t*)&hb);
            *(uint2*)(ol + idx) = make_uint2(*(uint32_t*)&la, *(uint32_t*)&lb);
        }
    }
}

// ---------------- depthwise causal conv: time-chunked sliding window ----------
// thread handles 4 channels x TS time steps; input silu computed ONCE per elem.
#define TS 16
template<bool IN_SILU>
__global__ void __launch_bounds__(256) dwconv_ts_k(
    const float* __restrict__ in, int ld,
    const float* __restrict__ w, const float* __restrict__ bias,
    float* __restrict__ out)
{
    int idx = blockIdx.x*256 + threadIdx.x;     // total = BATCH*(SEQ/TS)*(DI/4) = 65536
    int d4 = idx & 511;
    int rest = idx >> 9;
    int ch = rest & (SEQ/TS - 1);               // 0..63
    int b  = rest >> 6;
    int d  = d4*4;
    int s0 = ch*TS;
    const float* base = in + (size_t)b*SEQ*ld + d;
    float* obase = out + ((size_t)b*SEQ + s0)*DI + d;

    float4 wq[4];
    wq[0] = *(const float4*)(w + (size_t)(d+0)*4);
    wq[1] = *(const float4*)(w + (size_t)(d+1)*4);
    wq[2] = *(const float4*)(w + (size_t)(d+2)*4);
    wq[3] = *(const float4*)(w + (size_t)(d+3)*4);
    float4 bi = *(const float4*)(bias + d);

    auto ldx = [&](int t)->float4{
        if (t < 0) return make_float4(0.f,0.f,0.f,0.f);
        float4 v = *(const float4*)(base + (size_t)t*ld);
        if (IN_SILU){ v.x=siluf_(v.x); v.y=siluf_(v.y); v.z=siluf_(v.z); v.w=siluf_(v.w); }
        return v;
    };
    float4 p0 = ldx(s0-3), p1 = ldx(s0-2), p2 = ldx(s0-1);
    #pragma unroll
    for (int tt=0; tt<TS; tt++){
        float4 cur = ldx(s0+tt);
        float4 o;
        o.x = siluf_(bi.x + wq[0].x*p0.x + wq[0].y*p1.x + wq[0].z*p2.x + wq[0].w*cur.x);
        o.y = siluf_(bi.y + wq[1].x*p0.y + wq[1].y*p1.y + wq[1].z*p2.y + wq[1].w*cur.y);
        o.z = siluf_(bi.z + wq[2].x*p0.z + wq[2].y*p1.z + wq[2].z*p2.z + wq[2].w*cur.z);
        o.w = siluf_(bi.w + wq[3].x*p0.w + wq[3].y*p1.w + wq[3].z*p2.w + wq[3].w*cur.w);
        *(float4*)(obase + (size_t)tt*DI) = o;
        p0 = p1; p1 = p2; p2 = cur;
    }
}

// ---------------- x_proj (float4 dot products) --------------------------------
__global__ void __launch_bounds__(256) xproj_k(
    const float* __restrict__ xi, const float* __restrict__ W,
    float* __restrict__ proj)
{
    __shared__ float4 sA[DI/4];
    int tok = blockIdx.x;
    const float4* a = (const float4*)(xi + (size_t)tok*DI);
    for (int i=threadIdx.x; i<DI/4; i+=256) sA[i] = a[i];
    __syncthreads();
    int w = threadIdx.x >> 5, lane = threadIdx.x & 31;
    for (int j = w; j < 33; j += 8){
        const float4* Bw = (const float4*)(W + (size_t)j*DI);
        float s = 0.f;
        #pragma unroll 4
        for (int k = lane; k < DI/4; k += 32){
            float4 av = sA[k], bv = Bw[k];
            s = fmaf(av.x,bv.x, fmaf(av.y,bv.y, fmaf(av.z,bv.z, fmaf(av.w,bv.w, s))));
        }
        #pragma unroll
        for (int o=16;o;o>>=1) s += __shfl_xor_sync(0xffffffffu, s, o);
        if (lane==0) proj[(size_t)tok*33 + j] = s;
    }
}

// ---------------- selective scan ---------------------------------------------
#define TCH 64
__global__ void __launch_bounds__(128) scan_k(
    const float* __restrict__ proj, const float* __restrict__ xi,
    const float* __restrict__ dtw, const float* __restrict__ dtb,
    const float* __restrict__ Dp, float* __restrict__ y)
{
    int b = blockIdx.y;
    int d = blockIdx.x*128 + threadIdx.x;
    float w_dt = dtw[d];
    float b_dt = dtb[d];
    float Dd   = Dp[d];
    float h[Nst];
    #pragma unroll
    for (int n=0;n<Nst;n++) h[n]=0.f;

    __shared__ float sp[TCH][36];
    const float* projB = proj + (size_t)b*SEQ*33;
    const float* xiB   = xi   + (size_t)b*SEQ*DI + d;
    float*       yB    = y    + (size_t)b*SEQ*DI + d;

    for (int t0=0; t0<SEQ; t0+=TCH){
        __syncthreads();
        for (int i=threadIdx.x; i<TCH*33; i+=128){
            int t = i/33, j = i%33;
            int slot = (j==0) ? 0 : (j+3);
            sp[t][slot] = projB[(size_t)(t0)*33 + i];
        }
        __syncthreads();
        for (int tt=0; tt<TCH; tt++){
            int t = t0+tt;
            const float* r = sp[tt];
            float z = fmaf(r[0], w_dt, b_dt);
            float dt = (z > 15.f) ? z : __logf(1.f + __expf(z));
            float xv = xiB[(size_t)t*DI];
            float4 B0 = *(const float4*)&r[4];
            float4 B1 = *(const float4*)&r[8];
            float4 B2 = *(const float4*)&r[12];
            float4 B3 = *(const float4*)&r[16];
            float4 C0 = *(const float4*)&r[20];
            float4 C1 = *(const float4*)&r[24];
            float4 C2 = *(const float4*)&r[28];
            float4 C3 = *(const float4*)&r[32];
            float bArr[16] = {B0.x,B0.y,B0.z,B0.w,B1.x,B1.y,B1.z,B1.w,
                              B2.x,B2.y,B2.z,B2.w,B3.x,B3.y,B3.z,B3.w};
            float cArr[16] = {C0.x,C0.y,C0.z,C0.w,C1.x,C1.y,C1.z,C1.w,
                              C2.x,C2.y,C2.z,C2.w,C3.x,C3.y,C3.z,C3.w};
            float yv0=0.f, yv1=0.f, yv2=0.f, yv3=0.f;
            #pragma unroll
            for (int n=0;n<4;n++){
                float An;
                An = -(float)(n+1);
                float u0 = fmaf(h[n], An, xv * bArr[n]);
                h[n] = fmaf(dt, u0, h[n]);
                yv0 = fmaf(h[n], cArr[n], yv0);
                An = -(float)(n+5);
                float u1 = fmaf(h[n+4], An, xv * bArr[n+4]);
                h[n+4] = fmaf(dt, u1, h[n+4]);
                yv1 = fmaf(h[n+4], cArr[n+4], yv1);
                An = -(float)(n+9);
                float u2 = fmaf(h[n+8], An, xv * bArr[n+8]);
                h[n+8] = fmaf(dt, u2, h[n+8]);
                yv2 = fmaf(h[n+8], cArr[n+8], yv2);
                An = -(float)(n+13);
                float u3 = fmaf(h[n+12], An, xv * bArr[n+12]);
                h[n+12] = fmaf(dt, u3, h[n+12]);
                yv3 = fmaf(h[n+12], cArr[n+12], yv3);
            }
            float yv = (yv0+yv1) + (yv2+yv3);
            yB[(size_t)t*DI] = fmaf(xv, Dd, yv);
        }
    }
}

// ---------------- host side ---------------------------------------------------
static void* sym_addr_(const void* symbol){
    void* p = nullptr;
    cudaGetSymbolAddress(&p, symbol);
    return p;
}

template<int EPI>
static void launch_gemm(const __nv_bfloat16* Ah, const __nv_bfloat16* Al,
                        const __nv_bfloat16* Bh, const __nv_bfloat16* Bl,
                        float* C, int M, int N, int K,
                        const float* bias, const float* R1,
                        __nv_bfloat16* Oh, __nv_bfloat16* Ol){
    cudaFuncSetAttribute(mma_gemm_nt<EPI>, cudaFuncAttributeMaxDynamicSharedMemorySize, GSM);
    dim3 grid(N/BN, M/BM);
    mma_gemm_nt<EPI><<<grid, 256, GSM>>>(Ah, Al, Bh, Bl, C, M, N, K, bias, R1, Oh, Ol);
}

static void cvt(const float* src, __nv_bfloat16* hi, __nv_bfloat16* lo, int n){
    int n8 = n/8;
    cvt_hilo_k<<<(n8 + 255)/256, 256>>>((const float4*)src, (uint4*)hi, (uint4*)lo, n8);
}

extern "C" void kernel_launch(void* const* d_in, const int* in_sizes, int n_in,
                              void* d_out, int out_size)
{
    const float* hidden   = (const float*)d_in[0];
    const float* in_ng    = (const float*)d_in[1];
    const float* in_nb    = (const float*)d_in[2];
    const float* ln_g     = (const float*)d_in[3];
    const float* ln_b     = (const float*)d_in[4];
    const float* in_proj  = (const float*)d_in[5];   // (L, 2*DI, H)
    const float* conv_w   = (const float*)d_in[6];   // (L, 2, DI, K)
    const float* conv_b   = (const float*)d_in[7];   // (L, 2, DI)
    const float* x_proj   = (const float*)d_in[8];   // (L, 33, DI)
    const float* dt_w     = (const float*)d_in[9];   // (L, DI, 1)
    const float* dt_b     = (const float*)d_in[10];  // (L, DI)
    const float* Dparam   = (const float*)d_in[11];  // (L, DI)
    const float* mln_g    = (const float*)d_in[12];
    const float* mln_b    = (const float*)d_in[13];
    const float* out_proj = (const float*)d_in[14];  // (L, H, DI)
    const float* op1_w    = (const float*)d_in[15];
    const float* op1_b    = (const float*)d_in[16];
    const float* op2_w    = (const float*)d_in[17];
    const float* op2_b    = (const float*)d_in[18];
    float* out = (float*)d_out;

    float* x   = (float*)sym_addr_(g_x);
    float* xr  = (float*)sym_addr_(g_xr);
    float* c1  = (float*)sym_addr_(g_c1);
    float* xi  = (float*)sym_addr_(g_xi);
    float* pj  = (float*)sym_addr_(g_proj);
    float* yb  = (float*)sym_addr_(g_y);
    __nv_bfloat16* wh = (__nv_bfloat16*)sym_addr_(g_wh);
    __nv_bfloat16* wl = (__nv_bfloat16*)sym_addr_(g_wl);
    __nv_bfloat16* ah = (__nv_bfloat16*)sym_addr_(g_ah);
    __nv_bfloat16* al = (__nv_bfloat16*)sym_addr_(g_al);
    __nv_bfloat16* bh = (__nv_bfloat16*)sym_addr_(g_bh);
    __nv_bfloat16* bl = (__nv_bfloat16*)sym_addr_(g_bl);

    // weight pre-conversion (once per launch)
    cvt(in_proj,  wh + WOFF_IP, wl + WOFF_IP, Ld*2*DI*Hd);
    cvt(out_proj, wh + WOFF_OP, wl + WOFF_OP, Ld*Hd*DI);
    cvt(op1_w,    wh + WOFF_M1, wl + WOFF_M1, Hd*Hd);
    cvt(op2_w,    wh + WOFF_M2, wl + WOFF_M2, Hd*Hd);

    // x = LN(hidden)  (fp32)
    layernorm_k<Hd,0><<<TOK,256>>>(hidden, in_ng, in_nb, x, nullptr, nullptr, nullptr, 0, 0);

    for (int l=0; l<Ld; l++){
        // xn -> hi/lo
        layernorm_k<Hd,1><<<TOK,256>>>(x, ln_g + l*Hd, ln_b + l*Hd,
                                       nullptr, ah, al, nullptr, 0, 0);
        // xr = xn @ in_proj_w[l]^T
        launch_gemm<0>(ah, al,
                       wh + WOFF_IP + (size_t)l*2*DI*Hd, wl + WOFF_IP + (size_t)l*2*DI*Hd,
                       xr, TOK, 2*DI, Hd, nullptr, nullptr, nullptr, nullptr);
        // conv1 -> c1 ; conv2 -> xi
        {
            int blocks = (BATCH*(SEQ/TS)*(DI/4))/256;   // 256
            dwconv_ts_k<true><<<blocks,256>>>(
                xr, 2*DI,
                conv_w + (size_t)(l*2+0)*DI*Kc, conv_b + (size_t)(l*2+0)*DI, c1);
            dwconv_ts_k<false><<<blocks,256>>>(
                c1, DI,
                conv_w + (size_t)(l*2+1)*DI*Kc, conv_b + (size_t)(l*2+1)*DI, xi);
        }
        // proj = xi @ x_proj_w[l]^T
        xproj_k<<<TOK,256>>>(xi, x_proj + (size_t)l*33*DI, pj);
        // scan
        {
            dim3 grid(DI/128, BATCH);
            scan_k<<<grid,128>>>(pj, xi, dt_w + (size_t)l*DI, dt_b + (size_t)l*DI,
                                 Dparam + (size_t)l*DI, yb);
        }
        // y2 = LN_mamba(y) * sigmoid(res) -> hi/lo
        layernorm_k<DI,2><<<TOK,256>>>(yb, mln_g + (size_t)l*DI, mln_b + (size_t)l*DI,
                                       nullptr, ah, al, xr, 2*DI, DI);
        // x = x + y2 @ out_proj_w[l]^T ; last layer also emits hi/lo for MLP
        if (l < Ld-1){
            launch_gemm<2>(ah, al,
                           wh + WOFF_OP + (size_t)l*Hd*DI, wl + WOFF_OP + (size_t)l*Hd*DI,
                           x, TOK, Hd, DI, nullptr, x, nullptr, nullptr);
        } else {
            launch_gemm<4>(ah, al,
                           wh + WOFF_OP + (size_t)l*Hd*DI, wl + WOFF_OP + (size_t)l*Hd*DI,
                           x, TOK, Hd, DI, nullptr, x, bh, bl);
        }
    }

    // MLP (x already in bh/bl from last out_proj epilogue)
    launch_gemm<1>(bh, bl, wh + WOFF_M1, wl + WOFF_M1,
                   nullptr, TOK, Hd, Hd, op1_b, nullptr, ah, al);
    launch_gemm<3>(ah, al, wh + WOFF_M2, wl + WOFF_M2,
                   out, TOK, Hd, Hd, op2_b, hidden, nullptr, nullptr);
}